// round 16
// baseline (speedup 1.0000x reference)
#include <cuda_runtime.h>
#include <cuda_fp16.h>
#include <cstdint>

#define HHC 4096
#define OOC 4096
#define RRC 64
#define MTOT 16384
#define PIT 72   // fp16 smem pitch in halves (144 B)

// s1 smem (bytes), total 69632:
//   Xf32 stage s @ s*16384  : data 8192 | mask 8192      [0, 32768)
//   Xh buf b     @ 32768 + b*4608                        [32768, 41984)
//   A buf k      @ 41984 + k*9216                        [41984, 69632)
#define S1_XF(s)  ((uint32_t)(s) * 16384u)
#define S1_XH(b)  (32768u + (uint32_t)(b) * 4608u)
#define S1_AB(k)  (41984u + (uint32_t)(k) * 9216u)
#define SMEM_S1 69632
// s2 smem: Ts only
#define SMEM_S2 4608

// g_ah: linear [n][r][h] fp16
// g_bh: FRAGMENT-SWIZZLED fp16: block = (n, ot, s, j), 256 B each:
//   [lane(g,t4)][4 halves] = B[n][o=ot*16+j*8+g][k = s*16 + t4*2 + {0,1,8,9}]
__device__ __half g_ah[(size_t)8 * RRC * HHC];
__device__ __half g_bh[(size_t)8 * OOC * RRC];
__device__ float  g_tp[(size_t)2 * MTOT * RRC];

__device__ __forceinline__ void hmma16816(float* c,
                                          uint32_t a0, uint32_t a1, uint32_t a2, uint32_t a3,
                                          uint32_t b0, uint32_t b1) {
    asm volatile(
        "mma.sync.aligned.m16n8k16.row.col.f32.f16.f16.f32 "
        "{%0,%1,%2,%3}, {%4,%5,%6,%7}, {%8,%9}, {%0,%1,%2,%3};"
        : "+f"(c[0]), "+f"(c[1]), "+f"(c[2]), "+f"(c[3])
        : "r"(a0), "r"(a1), "r"(a2), "r"(a3), "r"(b0), "r"(b1));
}

__device__ __forceinline__ uint32_t h2u(__half2 h) {
    return *reinterpret_cast<uint32_t*>(&h);
}

__device__ __forceinline__ void cp16(uint32_t dst, const void* src) {
    asm volatile("cp.async.cg.shared.global [%0], [%1], 16;"
                 :: "r"(dst), "l"(src) : "memory");
}
#define CP_COMMIT() asm volatile("cp.async.commit_group;" ::: "memory")
#define CP_WAIT1()  asm volatile("cp.async.wait_group 1;" ::: "memory")

// ---------------- prep: A -> linear fp16 ; B -> fragment-swizzled fp16 ----------------
__global__ __launch_bounds__(256) void lora_prep(const float* __restrict__ la,
                                                 const float* __restrict__ lb) {
    const size_t NA = (size_t)8 * RRC * HHC / 4;   // 524288
    size_t i = (size_t)blockIdx.x * 256 + threadIdx.x;
    if (i < NA) {
        float4 a = ((const float4*)la)[i];
        __half2 h0 = __floats2half2_rn(a.x, a.y);
        __half2 h1 = __floats2half2_rn(a.z, a.w);
        ((uint2*)g_ah)[i] = make_uint2(h2u(h0), h2u(h1));
    } else {
        size_t j = i - NA;             // 0 .. 524287
        int lane = (int)(j & 31);
        int blk  = (int)(j >> 5);      // 16384 blocks: n(8) x ot(256) x s(4) x jb(2)
        int jb = blk & 1;
        int s  = (blk >> 1) & 3;
        int ot = (blk >> 3) & 255;
        int n  = blk >> 11;
        int g  = lane >> 2;
        int t4 = lane & 3;
        int o = ot * 16 + jb * 8 + g;
        int k = s * 16 + t4 * 2;
        const float* src = lb + ((size_t)n * OOC + o) * RRC + k;
        float2 f0 = *(const float2*)(src);       // k, k+1
        float2 f1 = *(const float2*)(src + 8);   // k+8, k+9
        __half2 h0 = __floats2half2_rn(f0.x, f0.y);
        __half2 h1 = __floats2half2_rn(f1.x, f1.y);
        ((uint2*)g_bh)[(size_t)blk * 32 + lane] = make_uint2(h2u(h0), h2u(h1));
    }
}

// ---------------- stage 1: T partials (K-split 2), all-async loads ----------------
__global__ __launch_bounds__(256, 3) void lora_s1(
    const float* __restrict__ data,
    const float* __restrict__ mask,
    const float* __restrict__ scalings)
{
    extern __shared__ char smem[];
    const uint32_t sbase = (uint32_t)__cvta_generic_to_shared(smem);

    const int t    = threadIdx.x;
    const int w    = t >> 5;
    const int lane = t & 31;
    const int g    = lane >> 2;
    const int t4   = lane & 3;

    const int wm = w & 1;          // M slab (16 rows of 32)
    const int wn = w >> 1;         // N slice (16 cols of 64)

    const int mt = blockIdx.x >> 1;
    const int sp = blockIdx.x & 1;        // K split
    const int m0 = mt * 32;
    const int n  = mt >> 6;               // 64 m-tiles per adapter
    const float sc = __ldg(scalings + n);
    const int hbase = sp * 2048;

    const int row0 = wm * 16 + g;

    float accT[2][4] = {};

    const float* dbase = data + (size_t)m0 * HHC + hbase;
    const float* mbase = mask + (size_t)m0 * HHC + hbase;
    const __half* ahb = g_ah + (size_t)n * RRC * HHC + hbase;

    const int ar = t >> 3, aq = t & 7;    // A loader rows ar, ar+32

    // ---- preamble: groups G0, G1 (X data+mask fp32, A fp16) ----
    #pragma unroll
    for (int p = 0; p < 2; p++) {
        const int ho = p * 64;
        #pragma unroll
        for (int i = 0; i < 2; i++) {
            int idx = t + i * 256;
            int row = idx >> 4, q = idx & 15;
            cp16(sbase + S1_XF(p) + (uint32_t)row * 256u + q * 16u,
                 dbase + (size_t)row * HHC + ho + q * 4);
            cp16(sbase + S1_XF(p) + 8192u + (uint32_t)row * 256u + q * 16u,
                 mbase + (size_t)row * HHC + ho + q * 4);
        }
        #pragma unroll
        for (int i = 0; i < 2; i++) {
            int row = ar + i * 32;
            cp16(sbase + S1_AB(p) + (uint32_t)row * 144u + aq * 16u,
                 ahb + (size_t)row * HHC + ho + aq * 8);
        }
        CP_COMMIT();
    }

    int abuf = 0;
    for (int ch = 0; ch < 32; ch++) {
        const int xst = ch & 1;

        CP_WAIT1();        // group ch landed
        __syncthreads();   // visible to all threads

        // ---- convert Xf32 -> fp16 Xh (fold mask & scaling) ----
        __half* Xs = (__half*)(smem + S1_XH(xst));
        #pragma unroll
        for (int i = 0; i < 2; i++) {
            int idx = t + i * 256;
            int row = idx >> 4, q = idx & 15;
            float4 d4 = *(const float4*)(smem + S1_XF(xst) + (uint32_t)row * 256u + q * 16u);
            float4 m4 = *(const float4*)(smem + S1_XF(xst) + 8192u + (uint32_t)row * 256u + q * 16u);
            __half2 h0 = __floats2half2_rn(d4.x * m4.x * sc, d4.y * m4.y * sc);
            __half2 h1 = __floats2half2_rn(d4.z * m4.z * sc, d4.w * m4.w * sc);
            *(uint2*)(Xs + row * PIT + q * 4) = make_uint2(h2u(h0), h2u(h1));
        }
        __syncthreads();   // Xh ready; Xf32(xst) consumed; A[(ch-1)%3] readers done

        // ---- issue G(ch+2): Xf32 stage (ch&1), A buf (abuf+2)%3 ----
        if (ch + 2 < 32) {
            const int ho = (ch + 2) * 64;
            int tbuf = abuf + 2; if (tbuf >= 3) tbuf -= 3;
            #pragma unroll
            for (int i = 0; i < 2; i++) {
                int idx = t + i * 256;
                int row = idx >> 4, q = idx & 15;
                cp16(sbase + S1_XF(xst) + (uint32_t)row * 256u + q * 16u,
                     dbase + (size_t)row * HHC + ho + q * 4);
                cp16(sbase + S1_XF(xst) + 8192u + (uint32_t)row * 256u + q * 16u,
                     mbase + (size_t)row * HHC + ho + q * 4);
            }
            #pragma unroll
            for (int i = 0; i < 2; i++) {
                int row = ar + i * 32;
                cp16(sbase + S1_AB(tbuf) + (uint32_t)row * 144u + aq * 16u,
                     ahb + (size_t)row * HHC + ho + aq * 8);
            }
        }
        CP_COMMIT();

        // ---- MMA: 4 k16 steps x 2 n-tiles ----
        const __half* Ah = (const __half*)(smem + S1_AB(abuf));
        #pragma unroll
        for (int s = 0; s < 4; s++) {
            const int kb = s * 16 + t4 * 2;
            uint32_t a0 = *(const uint32_t*)(Xs + row0 * PIT + kb);
            uint32_t a1 = *(const uint32_t*)(Xs + (row0 + 8) * PIT + kb);
            uint32_t a2 = *(const uint32_t*)(Xs + row0 * PIT + kb + 8);
            uint32_t a3 = *(const uint32_t*)(Xs + (row0 + 8) * PIT + kb + 8);
            #pragma unroll
            for (int j = 0; j < 2; j++) {
                const int nr = wn * 16 + j * 8 + g;
                uint32_t b0 = *(const uint32_t*)(Ah + nr * PIT + kb);
                uint32_t b1 = *(const uint32_t*)(Ah + nr * PIT + kb + 8);
                hmma16816(accT[j], a0, a1, a2, a3, b0, b1);
            }
        }
        abuf++; if (abuf == 3) abuf = 0;
    }

    // ---- write fp32 partial T ----
    float* tp = g_tp + (size_t)sp * MTOT * RRC;
    #pragma unroll
    for (int j = 0; j < 2; j++) {
        const int c = wn * 16 + j * 8 + t4 * 2;
        *(float2*)(tp + (size_t)(m0 + row0) * RRC + c) =
            make_float2(accT[j][0], accT[j][1]);
        *(float2*)(tp + (size_t)(m0 + row0 + 8) * RRC + c) =
            make_float2(accT[j][2], accT[j][3]);
    }
}

// ---------------- stage 2: out = result + T @ B^T (o-split 4) ----------------
// Barrier-free main loop: B fragments direct from swizzled global (L2-hot),
// register-prefetched one iteration ahead. No smem in the loop.
__global__ __launch_bounds__(256, 3) void lora_s2(
    const float* __restrict__ result,
    float* __restrict__ out)
{
    extern __shared__ char smem[];

    const int t    = threadIdx.x;
    const int w    = t >> 5;
    const int lane = t & 31;
    const int g    = lane >> 2;
    const int t4   = lane & 3;

    const int wm = w & 1;
    const int wn = w >> 1;

    const int mt  = blockIdx.x & 511;
    const int osp = blockIdx.x >> 9;      // o split 0..3, 1024 cols each
    const int m0 = mt * 32;
    const int n  = mt >> 6;
    const int obase0 = osp * 1024;

    const int row0 = wm * 16 + g;

    // ---- combine T partials -> fp16 Ts ----
    __half* Ts = (__half*)smem;
    {
        const int row = t >> 3;
        const int c8  = (t & 7) * 8;
        const float* p0 = g_tp + (size_t)(m0 + row) * RRC + c8;
        const float* p1 = p0 + (size_t)MTOT * RRC;
        float4 a0 = *(const float4*)(p0);
        float4 a1 = *(const float4*)(p0 + 4);
        float4 b0 = *(const float4*)(p1);
        float4 b1 = *(const float4*)(p1 + 4);
        __half2 h0 = __floats2half2_rn(a0.x + b0.x, a0.y + b0.y);
        __half2 h1 = __floats2half2_rn(a0.z + b0.z, a0.w + b0.w);
        __half2 h2 = __floats2half2_rn(a1.x + b1.x, a1.y + b1.y);
        __half2 h3 = __floats2half2_rn(a1.z + b1.z, a1.w + b1.w);
        *(uint4*)(Ts + row * PIT + c8) = make_uint4(h2u(h0), h2u(h1), h2u(h2), h2u(h3));
    }
    __syncthreads();

    // ---- hoist T fragments ----
    uint32_t ta[4][4];
    #pragma unroll
    for (int s = 0; s < 4; s++) {
        const int kb = s * 16 + t4 * 2;
        ta[s][0] = *(const uint32_t*)(Ts + row0 * PIT + kb);
        ta[s][1] = *(const uint32_t*)(Ts + (row0 + 8) * PIT + kb);
        ta[s][2] = *(const uint32_t*)(Ts + row0 * PIT + kb + 8);
        ta[s][3] = *(const uint32_t*)(Ts + (row0 + 8) * PIT + kb + 8);
    }

    // swizzled B base: ot = osp*64 + oc*4 + wn; block = (n*256+ot)*8 + s*2+j
    const uint2* bfw = (const uint2*)g_bh
        + ((size_t)(n * 256 + osp * 64 + wn) * 8u) * 32u + lane;

    // ---- preload oc=0: B fragments + residual ----
    uint2 bf[4][2];
    #pragma unroll
    for (int s = 0; s < 4; s++)
        #pragma unroll
        for (int j = 0; j < 2; j++)
            bf[s][j] = __ldg(bfw + (size_t)(s * 2 + j) * 32u);

    float2 rcur[2][2];
    #pragma unroll
    for (int j = 0; j < 2; j++) {
        const int ocol = obase0 + wn * 16 + j * 8 + t4 * 2;
        rcur[j][0] = __ldcs((const float2*)(result + (size_t)(m0 + row0) * OOC + ocol));
        rcur[j][1] = __ldcs((const float2*)(result + (size_t)(m0 + row0 + 8) * OOC + ocol));
    }

    for (int oc = 0; oc < 16; oc++) {
        const int o0 = obase0 + oc * 64;

        // ---- prefetch next iteration: B frags (L2-hot) + residual (DRAM) ----
        uint2 bfn[4][2];
        float2 rnxt[2][2];
        if (oc + 1 < 16) {
            const uint2* bb = bfw + (size_t)(oc + 1) * 1024u;
            #pragma unroll
            for (int s = 0; s < 4; s++)
                #pragma unroll
                for (int j = 0; j < 2; j++)
                    bfn[s][j] = __ldg(bb + (size_t)(s * 2 + j) * 32u);
            const int ob = o0 + 64;
            #pragma unroll
            for (int j = 0; j < 2; j++) {
                const int ocol = ob + wn * 16 + j * 8 + t4 * 2;
                rnxt[j][0] = __ldcs((const float2*)(result + (size_t)(m0 + row0) * OOC + ocol));
                rnxt[j][1] = __ldcs((const float2*)(result + (size_t)(m0 + row0 + 8) * OOC + ocol));
            }
        }

        // ---- MMA ----
        float acc[2][4] = {};
        #pragma unroll
        for (int s = 0; s < 4; s++)
            #pragma unroll
            for (int j = 0; j < 2; j++)
                hmma16816(acc[j], ta[s][0], ta[s][1], ta[s][2], ta[s][3],
                          bf[s][j].x, bf[s][j].y);

        // ---- epilogue ----
        #pragma unroll
        for (int j = 0; j < 2; j++) {
            const int ocol = o0 + wn * 16 + j * 8 + t4 * 2;
            size_t gi0 = (size_t)(m0 + row0) * OOC + ocol;
            size_t gi1 = (size_t)(m0 + row0 + 8) * OOC + ocol;
            __stcs((float2*)(out + gi0),
                   make_float2(rcur[j][0].x + acc[j][0], rcur[j][0].y + acc[j][1]));
            __stcs((float2*)(out + gi1),
                   make_float2(rcur[j][1].x + acc[j][2], rcur[j][1].y + acc[j][3]));
        }

        // rotate prefetched values
        #pragma unroll
        for (int s = 0; s < 4; s++)
            #pragma unroll
            for (int j = 0; j < 2; j++)
                bf[s][j] = bfn[s][j];
        #pragma unroll
        for (int j = 0; j < 2; j++) {
            rcur[j][0] = rnxt[j][0];
            rcur[j][1] = rnxt[j][1];
        }
    }
}

extern "C" void kernel_launch(void* const* d_in, const int* in_sizes, int n_in,
                              void* d_out, int out_size) {
    const float* result   = (const float*)d_in[0];
    const float* data     = (const float*)d_in[1];
    const float* mask     = (const float*)d_in[2];
    const float* lora_a   = (const float*)d_in[3];
    const float* lora_b   = (const float*)d_in[4];
    const float* scalings = (const float*)d_in[5];
    float* out = (float*)d_out;

    lora_prep<<<4096, 256>>>(lora_a, lora_b);

    cudaFuncSetAttribute(lora_s1, cudaFuncAttributeMaxDynamicSharedMemorySize, SMEM_S1);
    cudaFuncSetAttribute(lora_s2, cudaFuncAttributeMaxDynamicSharedMemorySize, SMEM_S2);

    lora_s1<<<1024, 256, SMEM_S1>>>(data, mask, scalings);
    lora_s2<<<2048, 256, SMEM_S2>>>(result, out);
}

// round 17
// speedup vs baseline: 1.0191x; 1.0191x over previous
#include <cuda_runtime.h>
#include <cuda_fp16.h>
#include <cstdint>

#define HHC 4096
#define OOC 4096
#define RRC 64
#define PIT 72   // smem pitch in halves (144 B)

// smem (bytes):
//   phase1: Xbuf[b]=b*4608  [0,9216) ; Abuf[k]=9216+k*9216  [9216,36864)
//   phase2: Bbuf[k]=k*9216  [0,27648)   (overlaps X/A after final phase-1 sync)
//   Ts @ 36864  [36864,41472)
#define SMEM_TOTAL 41472

// pre-converted fp16 weights (4 MB each)
__device__ __half g_ah[(size_t)8 * RRC * HHC];
__device__ __half g_bh[(size_t)8 * OOC * RRC];

__device__ __forceinline__ void hmma16816(float* c,
                                          uint32_t a0, uint32_t a1, uint32_t a2, uint32_t a3,
                                          uint32_t b0, uint32_t b1) {
    asm volatile(
        "mma.sync.aligned.m16n8k16.row.col.f32.f16.f16.f32 "
        "{%0,%1,%2,%3}, {%4,%5,%6,%7}, {%8,%9}, {%0,%1,%2,%3};"
        : "+f"(c[0]), "+f"(c[1]), "+f"(c[2]), "+f"(c[3])
        : "r"(a0), "r"(a1), "r"(a2), "r"(a3), "r"(b0), "r"(b1));
}

__device__ __forceinline__ uint32_t h2u(__half2 h) {
    return *reinterpret_cast<uint32_t*>(&h);
}

__device__ __forceinline__ void cp16(uint32_t dst, const void* src) {
    asm volatile("cp.async.cg.shared.global [%0], [%1], 16;"
                 :: "r"(dst), "l"(src) : "memory");
}
#define CP_COMMIT() asm volatile("cp.async.commit_group;" ::: "memory")
#define CP_WAIT1()  asm volatile("cp.async.wait_group 1;" ::: "memory")

// ---------------- prep: convert lora_a / lora_b to fp16, MLP-8 ----------------
// 1048576 float4 total (A then B); 512 blocks x 256 threads x 8 each.
__global__ __launch_bounds__(256) void lora_prep(const float* __restrict__ la,
                                                 const float* __restrict__ lb) {
    const size_t NA = (size_t)8 * RRC * HHC / 4;   // 524288 float4 in A
    const size_t base = (size_t)blockIdx.x * 2048 + threadIdx.x;

    float4 v[8];
    #pragma unroll
    for (int q = 0; q < 8; q++) {
        size_t i = base + (size_t)q * 256;
        v[q] = (i < NA) ? ((const float4*)la)[i] : ((const float4*)lb)[i - NA];
    }
    #pragma unroll
    for (int q = 0; q < 8; q++) {
        size_t i = base + (size_t)q * 256;
        __half2 h0 = __floats2half2_rn(v[q].x, v[q].y);
        __half2 h1 = __floats2half2_rn(v[q].z, v[q].w);
        uint2 pk = make_uint2(h2u(h0), h2u(h1));
        if (i < NA) ((uint2*)g_ah)[i] = pk;
        else        ((uint2*)g_bh)[i - NA] = pk;
    }
}

// ---------------- fused LoRA (R12 configuration — best measured) ----------------
__global__ __launch_bounds__(256, 4) void lora_fused(
    const float* __restrict__ result,
    const float* __restrict__ data,
    const float* __restrict__ mask,
    const float* __restrict__ scalings,
    float* __restrict__ out)
{
    extern __shared__ char smem[];
    const uint32_t sbase = (uint32_t)__cvta_generic_to_shared(smem);

    const int t    = threadIdx.x;
    const int w    = t >> 5;
    const int lane = t & 31;
    const int g    = lane >> 2;
    const int t4   = lane & 3;

    const int wm = w & 1;          // M slab (16 rows of 32)
    const int wn = w >> 1;         // N slice (16 cols of 64)

    const int m0 = blockIdx.x * 32;
    const int n  = blockIdx.x >> 6;       // 64 CTAs per adapter
    const float sc = __ldg(scalings + n);

    const int row0 = wm * 16 + g;

    // ======================== PHASE 1: depth-2 A pipeline ========================
    float accT[2][4] = {};

    const float* dbase = data + (size_t)m0 * HHC;
    const float* mbase = mask + (size_t)m0 * HHC;
    const __half* ahb = g_ah + (size_t)n * RRC * HHC;

    const int xr = t >> 4, xq = t & 15;
    const int ar = t >> 3, aq = t & 7;

    // preamble: A chunks 0 and 1 as two separate groups
    #pragma unroll
    for (int i = 0; i < 2; i++) {
        int row = ar + i * 32;
        cp16(sbase + 9216u + (uint32_t)row * 144u + aq * 16u,
             ahb + (size_t)row * HHC + aq * 8);
    }
    CP_COMMIT();
    #pragma unroll
    for (int i = 0; i < 2; i++) {
        int row = ar + i * 32;
        cp16(sbase + 9216u + 9216u + (uint32_t)row * 144u + aq * 16u,
             ahb + (size_t)row * HHC + 64 + aq * 8);
    }
    CP_COMMIT();

    float4 dreg[2], mreg[2];
    #pragma unroll
    for (int i = 0; i < 2; i++) {
        int row = xr + i * 16;
        dreg[i] = __ldcs((const float4*)(dbase + (size_t)row * HHC) + xq);
        mreg[i] = __ldcs((const float4*)(mbase + (size_t)row * HHC) + xq);
    }

    int abuf = 0;
    for (int ch = 0; ch < 64; ch++) {
        const int xb = ch & 1;
        __half* Xs = (__half*)(smem + xb * 4608);
        const __half* Ah = (const __half*)(smem + 9216 + abuf * 9216);

        #pragma unroll
        for (int i = 0; i < 2; i++) {
            int row = xr + i * 16;
            float4 d4 = dreg[i], m4 = mreg[i];
            __half2 h0 = __floats2half2_rn(d4.x * m4.x * sc, d4.y * m4.y * sc);
            __half2 h1 = __floats2half2_rn(d4.z * m4.z * sc, d4.w * m4.w * sc);
            *(uint2*)(Xs + row * PIT + xq * 4) = make_uint2(h2u(h0), h2u(h1));
        }
        CP_WAIT1();
        __syncthreads();

        if (ch + 2 < 64) {
            const int ho = (ch + 2) * 64;
            int tbuf = abuf + 2; if (tbuf >= 3) tbuf -= 3;
            #pragma unroll
            for (int i = 0; i < 2; i++) {
                int row = ar + i * 32;
                cp16(sbase + 9216u + (uint32_t)tbuf * 9216u + (uint32_t)row * 144u + aq * 16u,
                     ahb + (size_t)row * HHC + ho + aq * 8);
            }
        }
        CP_COMMIT();

        if (ch + 1 < 64) {
            const int ho = (ch + 1) * 64;
            #pragma unroll
            for (int i = 0; i < 2; i++) {
                int row = xr + i * 16;
                dreg[i] = __ldcs((const float4*)(dbase + (size_t)row * HHC + ho) + xq);
                mreg[i] = __ldcs((const float4*)(mbase + (size_t)row * HHC + ho) + xq);
            }
        }

        #pragma unroll
        for (int s = 0; s < 4; s++) {
            const int kb = s * 16 + t4 * 2;
            uint32_t a0 = *(const uint32_t*)(Xs + row0 * PIT + kb);
            uint32_t a1 = *(const uint32_t*)(Xs + (row0 + 8) * PIT + kb);
            uint32_t a2 = *(const uint32_t*)(Xs + row0 * PIT + kb + 8);
            uint32_t a3 = *(const uint32_t*)(Xs + (row0 + 8) * PIT + kb + 8);
            #pragma unroll
            for (int j = 0; j < 2; j++) {
                const int nr = wn * 16 + j * 8 + g;
                uint32_t b0 = *(const uint32_t*)(Ah + nr * PIT + kb);
                uint32_t b1 = *(const uint32_t*)(Ah + nr * PIT + kb + 8);
                hmma16816(accT[j], a0, a1, a2, a3, b0, b1);
            }
        }
        abuf++; if (abuf == 3) abuf = 0;
    }

    // ---- quantize T into smem ----
    __half* Ts = (__half*)(smem + 36864);
    #pragma unroll
    for (int j = 0; j < 2; j++) {
        const int c = wn * 16 + j * 8 + t4 * 2;
        __half2 h0 = __floats2half2_rn(accT[j][0], accT[j][1]);
        __half2 h1 = __floats2half2_rn(accT[j][2], accT[j][3]);
        *(uint32_t*)(Ts + row0 * PIT + c)       = h2u(h0);
        *(uint32_t*)(Ts + (row0 + 8) * PIT + c) = h2u(h1);
    }
    __syncthreads();   // Ts published; all phase1 smem reads done

    // ======================== PHASE 2: depth-2 B pipeline + 2-deep residual ========================
    uint32_t ta[4][4];
    #pragma unroll
    for (int s = 0; s < 4; s++) {
        const int kb = s * 16 + t4 * 2;
        ta[s][0] = *(const uint32_t*)(Ts + row0 * PIT + kb);
        ta[s][1] = *(const uint32_t*)(Ts + (row0 + 8) * PIT + kb);
        ta[s][2] = *(const uint32_t*)(Ts + row0 * PIT + kb + 8);
        ta[s][3] = *(const uint32_t*)(Ts + (row0 + 8) * PIT + kb + 8);
    }

    const __half* bhb = g_bh + (size_t)n * OOC * RRC;
    const int br = t >> 3, bq = t & 7;

    // preamble: B oc 0 and oc 1, two groups
    #pragma unroll
    for (int i = 0; i < 2; i++) {
        int row = br + i * 32;
        cp16(sbase + (uint32_t)row * 144u + bq * 16u,
             bhb + (size_t)row * RRC + bq * 8);
    }
    CP_COMMIT();
    #pragma unroll
    for (int i = 0; i < 2; i++) {
        int row = br + i * 32;
        cp16(sbase + 9216u + (uint32_t)row * 144u + bq * 16u,
             bhb + (size_t)(64 + row) * RRC + bq * 8);
    }
    CP_COMMIT();

    // preamble: residuals for oc 0 and oc 1
    float2 rcur[2][2], rnxt[2][2];
    #pragma unroll
    for (int j = 0; j < 2; j++) {
        const int ocol = wn * 16 + j * 8 + t4 * 2;
        rcur[j][0] = __ldcs((const float2*)(result + (size_t)(m0 + row0) * OOC + ocol));
        rcur[j][1] = __ldcs((const float2*)(result + (size_t)(m0 + row0 + 8) * OOC + ocol));
        rnxt[j][0] = __ldcs((const float2*)(result + (size_t)(m0 + row0) * OOC + 64 + ocol));
        rnxt[j][1] = __ldcs((const float2*)(result + (size_t)(m0 + row0 + 8) * OOC + 64 + ocol));
    }

    int bbuf = 0;
    for (int oc = 0; oc < 64; oc++) {
        const __half* Bh = (const __half*)(smem + bbuf * 9216);
        const int o0 = oc * 64;

        CP_WAIT1();
        __syncthreads();

        if (oc + 2 < 64) {
            const int on = (oc + 2) * 64;
            int tbuf = bbuf + 2; if (tbuf >= 3) tbuf -= 3;
            #pragma unroll
            for (int i = 0; i < 2; i++) {
                int row = br + i * 32;
                cp16(sbase + (uint32_t)tbuf * 9216u + (uint32_t)row * 144u + bq * 16u,
                     bhb + (size_t)(on + row) * RRC + bq * 8);
            }
        }
        CP_COMMIT();

        float2 rnx2[2][2];
        if (oc + 2 < 64) {
            const int ob = o0 + 128;
            #pragma unroll
            for (int j = 0; j < 2; j++) {
                const int ocol = ob + wn * 16 + j * 8 + t4 * 2;
                rnx2[j][0] = __ldcs((const float2*)(result + (size_t)(m0 + row0) * OOC + ocol));
                rnx2[j][1] = __ldcs((const float2*)(result + (size_t)(m0 + row0 + 8) * OOC + ocol));
            }
        }

        float acc[2][4] = {};
        #pragma unroll
        for (int s = 0; s < 4; s++) {
            const int kb = s * 16 + t4 * 2;
            #pragma unroll
            for (int j = 0; j < 2; j++) {
                const int nr = wn * 16 + j * 8 + g;
                uint32_t b0 = *(const uint32_t*)(Bh + nr * PIT + kb);
                uint32_t b1 = *(const uint32_t*)(Bh + nr * PIT + kb + 8);
                hmma16816(acc[j], ta[s][0], ta[s][1], ta[s][2], ta[s][3], b0, b1);
            }
        }

        #pragma unroll
        for (int j = 0; j < 2; j++) {
            const int ocol = o0 + wn * 16 + j * 8 + t4 * 2;
            size_t gi0 = (size_t)(m0 + row0) * OOC + ocol;
            size_t gi1 = (size_t)(m0 + row0 + 8) * OOC + ocol;
            __stcs((float2*)(out + gi0),
                   make_float2(rcur[j][0].x + acc[j][0], rcur[j][0].y + acc[j][1]));
            __stcs((float2*)(out + gi1),
                   make_float2(rcur[j][1].x + acc[j][2], rcur[j][1].y + acc[j][3]));
        }
        #pragma unroll
        for (int j = 0; j < 2; j++) {
            rcur[j][0] = rnxt[j][0]; rcur[j][1] = rnxt[j][1];
            rnxt[j][0] = rnx2[j][0]; rnxt[j][1] = rnx2[j][1];
        }
        bbuf++; if (bbuf == 3) bbuf = 0;
    }
}

extern "C" void kernel_launch(void* const* d_in, const int* in_sizes, int n_in,
                              void* d_out, int out_size) {
    const float* result   = (const float*)d_in[0];
    const float* data     = (const float*)d_in[1];
    const float* mask     = (const float*)d_in[2];
    const float* lora_a   = (const float*)d_in[3];
    const float* lora_b   = (const float*)d_in[4];
    const float* scalings = (const float*)d_in[5];
    float* out = (float*)d_out;

    lora_prep<<<512, 256>>>(lora_a, lora_b);

    cudaFuncSetAttribute(lora_fused, cudaFuncAttributeMaxDynamicSharedMemorySize, SMEM_TOTAL);
    lora_fused<<<512, 256, SMEM_TOTAL>>>(result, data, mask, scalings, out);
}